// round 5
// baseline (speedup 1.0000x reference)
#include <cuda_runtime.h>
#include <math.h>

// Problem shapes (fixed): x (4,1,512,180) float32 -> out (4,1,512,512) float32
#define NB   4
#define H    512
#define WIN  180
#define L    180
#define W    512

// Padded pair table: index k = (b+1) + PAD, zeros outside valid core.
// Entries pre-rescaled: (P[b] - b*dP, dP) so sample = q.x + iy*q.y (iy global).
#define PAD      112
#define PSTRIDE2 744

__device__ static float2 g_pairs[NB * L * PSTRIDE2];
__device__ static float2 g_trig[L];   // (ca, sa) = 255.5*(cos, sin)

// ---------------------------------------------------------------------------
// Prep: per (n,l) blend the two sinogram columns selected by gx (fp32 math
// replicating the reference), then emit globally-rescaled pairs.
// ---------------------------------------------------------------------------
__global__ void irad_prep(const float* __restrict__ x) {
    const int l = blockIdx.x;
    const int n = blockIdx.y;
    __shared__ float col[H];

    float Xc  = fmaf((float)l, 2.0f / 179.0f, -1.0f);
    float ix  = (Xc + 1.0f) * 0.5f * 179.0f;
    float i0f = floorf(ix);
    float wx1 = ix - i0f;
    float wx0 = 1.0f - wx1;
    int   i0  = (int)i0f;
    int   i1  = i0 + 1;
    bool  v0  = (i0 >= 0) && (i0 <= WIN - 1);
    bool  v1  = (i1 >= 0) && (i1 <= WIN - 1);

    const float* xn = x + (size_t)n * H * WIN;
    for (int r = threadIdx.x; r < H; r += blockDim.x) {
        float a = v0 ? xn[r * WIN + i0] : 0.0f;
        float b = v1 ? xn[r * WIN + i1] : 0.0f;
        col[r] = wx0 * a + wx1 * b;
    }
    if (threadIdx.x == 0 && n == 0) {
        float rad = (float)l * (3.14159265358979323846f / 180.0f);
        g_trig[l] = make_float2(cosf(rad) * 255.5f, sinf(rad) * 255.5f);
    }
    __syncthreads();

    float2* pr = g_pairs + (size_t)(n * L + l) * PSTRIDE2;
    for (int k = threadIdx.x; k < PSTRIDE2; k += blockDim.x) {
        int kk = k - PAD;                                    // = b+1
        float P  = (kk >= 1 && kk <= 512) ? col[kk - 1] : 0.0f;
        float Pn = (kk >= 0 && kk <= 511) ? col[kk]     : 0.0f;
        float d  = Pn - P;
        // global rescale: value(iy) = q.x + iy*q.y for floor(iy) = kk-1
        pr[k] = make_float2(fmaf(-(float)(kk - 1), d, P), d);
    }
}

// ---------------------------------------------------------------------------
// Main: 32x32 tile, 128 threads, 8 px/thread. Double-buffered angle chunks
// prefetched with cp.async. Inner loop: 6 issue slots per sample.
// ---------------------------------------------------------------------------
#define TJ   32
#define TI   32
#define CH   30     // angles per chunk (180 = 6*30)
#define NCH  (L / CH)
#define WMAX 48

__device__ __forceinline__ void cp_async8(unsigned dst, const void* src) {
    asm volatile("cp.async.ca.shared.global [%0], [%1], 8;\n"
                 :: "r"(dst), "l"(src));
}
__device__ __forceinline__ void cp_async_commit() {
    asm volatile("cp.async.commit_group;\n");
}
__device__ __forceinline__ void cp_async_wait_all() {
    asm volatile("cp.async.wait_group 0;\n");
}

__global__ void __launch_bounds__(128) irad_main(float* __restrict__ out) {
    __shared__ float2 sP[2 * CH * WMAX];
    __shared__ float4 sMeta[2 * CH];   // (ca, -sa, as_float(ab), unused)

    const int n    = blockIdx.z;
    const int j0   = blockIdx.x * TJ;
    const int i0t  = blockIdx.y * TI;
    const int t    = threadIdx.x;
    const int lane = t & 31;
    const int wid  = t >> 5;           // 0..3
    const int j    = j0 + lane;

    const float uj = fmaf((float)j, 2.0f / 511.0f, -1.0f);

    float ui[8], acc[8];
#pragma unroll
    for (int k = 0; k < 8; k++) {
        ui[k]  = fmaf((float)(i0t + wid + 4 * k), 2.0f / 511.0f, -1.0f);
        acc[k] = 0.0f;
    }

    const float uj0 = fmaf((float)j0,           2.0f / 511.0f, -1.0f);
    const float uj1 = fmaf((float)(j0 + TJ-1),  2.0f / 511.0f, -1.0f);
    const float vi0 = fmaf((float)i0t,          2.0f / 511.0f, -1.0f);
    const float vi1 = fmaf((float)(i0t + TI-1), 2.0f / 511.0f, -1.0f);

    const float2* gp = g_pairs + (size_t)n * L * PSTRIDE2;
    const unsigned sPb = (unsigned)__cvta_generic_to_shared(sP);

    // ---- stage(chunk c into buffer b): pure cp.async copies + meta ----
    auto stage = [&](int c, int b) {
        const int c0 = c * CH;
        const int bofs = b * CH;
        for (int lc = wid; lc < CH; lc += 4) {
            const int l = c0 + lc;
            float2 tr = g_trig[l];
            float ca = tr.x, sa = tr.y;

            float jlo = fminf(ca * uj0, ca * uj1);
            float jhi = fmaxf(ca * uj0, ca * uj1);
            float ilo = fminf(sa * vi0, sa * vi1);
            float ihi = fmaxf(sa * vi0, sa * vi1);
            float iymin = 255.5f + jlo - ihi;
            float iymax = 255.5f + jhi - ilo;

            int ws  = (int)floorf(iymin);
            int cnt = (int)floorf(iymax) + 3 - ws;           // <= 47

            const float2* src = gp + (size_t)l * PSTRIDE2 + (ws + PAD);
            unsigned dst = sPb + (unsigned)((bofs + lc) * WMAX) * 8u;
            for (int e = lane; e < cnt; e += 32)
                cp_async8(dst + (unsigned)e * 8u, src + e);
            if (lane == 0) {
                int ab = (bofs + lc) * WMAX + 1 - ws;        // smem idx = ab + floor(iy)
                sMeta[bofs + lc] = make_float4(ca, -sa, __int_as_float(ab), 0.0f);
            }
        }
        cp_async_commit();
    };

    stage(0, 0);

    for (int c = 0; c < NCH; c++) {
        const int b = c & 1;
        cp_async_wait_all();
        __syncthreads();                       // buf b ready; buf b^1 free

        if (c + 1 < NCH) stage(c + 1, b ^ 1);  // issue-only prefetch

        const float4* mp = sMeta + b * CH;
#pragma unroll 2
        for (int lc = 0; lc < CH; lc++) {
            const float4 m   = mp[lc];
            const float2* pa = sP + __float_as_int(m.z);
            const float t0   = fmaf(m.x, uj, 255.5f);
#pragma unroll
            for (int k = 0; k < 8; k++) {
                float iy = fmaf(m.y, ui[k], t0);
                int   e  = __float2int_rd(iy);
                float2 q = pa[e];
                acc[k] = fmaf(iy, q.y, acc[k] + q.x);
            }
        }
    }

    const float scale = (float)(M_PI / 360.0);   // pi / (2*L)
    float* po = out + ((size_t)(n * W + i0t + wid) * W) + j;
#pragma unroll
    for (int k = 0; k < 8; k++) {
        po[(size_t)(4 * k) * W] = acc[k] * scale;
    }
}

// ---------------------------------------------------------------------------
extern "C" void kernel_launch(void* const* d_in, const int* in_sizes, int n_in,
                              void* d_out, int out_size) {
    const float* x = (const float*)d_in[0];
    float* out = (float*)d_out;
    (void)in_sizes; (void)n_in; (void)out_size;

    irad_prep<<<dim3(L, NB), 128>>>(x);
    irad_main<<<dim3(W / TJ, W / TI, NB), 128>>>(out);
}